// round 5
// baseline (speedup 1.0000x reference)
#include <cuda_runtime.h>

#define D 4096
#define NV4 (D / 4)        // 1024 float4 per row
#define THREADS 256
#define GRID 912           // 152 SMs * 6 CTAs/SM -> single persistent wave
#define EPS 1e-6f

__global__ __launch_bounds__(THREADS, 6) void mrmsnorm_kernel(
    const float4* __restrict__ x,
    const float4* __restrict__ scale,
    float4* __restrict__ out,
    int rows)
{
    __shared__ float ws[2][8][3];

    const int t = threadIdx.x;
    const int warp = t >> 5;
    const int lane = t & 31;

    // scale is small and L1/L2-resident after the first row; load once.
    const float4 s0 = __ldg(&scale[t]);
    const float4 s1 = __ldg(&scale[t + THREADS]);
    const float4 s2 = __ldg(&scale[t + 2 * THREADS]);
    const float4 s3 = __ldg(&scale[t + 3 * THREADS]);

    int p = 0;
    #pragma unroll 1
    for (int row = blockIdx.x; row < rows; row += GRID, p ^= 1) {
        const float4* __restrict__ xr = x + (size_t)row * NV4;
        float4* __restrict__ orow = out + (size_t)row * NV4;

        // Four front-batched streaming loads (x is read exactly once).
        float4 a = __ldcs(&xr[t]);
        float4 b = __ldcs(&xr[t + THREADS]);
        float4 c = __ldcs(&xr[t + 2 * THREADS]);
        float4 d = __ldcs(&xr[t + 3 * THREADS]);

        float sa  = a.x * a.x + a.y * a.y + a.z * a.z + a.w * a.w;
        float sb  = b.x * b.x + b.y * b.y + b.z * b.z + b.w * b.w;
        float sc  = c.x * c.x + c.y * c.y + c.z * c.z + c.w * c.w;
        float sd  = d.x * d.x + d.y * d.y + d.z * d.z + d.w * d.w;
        float scd = sc + sd;

        #pragma unroll
        for (int o = 16; o > 0; o >>= 1) {
            sa  += __shfl_down_sync(0xffffffffu, sa, o);
            sb  += __shfl_down_sync(0xffffffffu, sb, o);
            scd += __shfl_down_sync(0xffffffffu, scd, o);
        }

        if (lane == 0) {
            ws[p][warp][0] = sa;
            ws[p][warp][1] = sb;
            ws[p][warp][2] = scd;
        }
        __syncthreads();   // only barrier per row (parity protects WAR)

        // Segment sums; float4-index ranges: seg0 [0,64) (warps 0-1),
        // seg1 [64,128) (warps 2-3), seg2 [128,256) (warps 4-7),
        // seg3 [256,512) (slice b), seg4 [512,1024) (slices c,d).
        float seg0 = ws[p][0][0] + ws[p][1][0];
        float seg1 = ws[p][2][0] + ws[p][3][0];
        float seg2 = ws[p][4][0] + ws[p][5][0] + ws[p][6][0] + ws[p][7][0];
        float seg3 = ws[p][0][1] + ws[p][1][1] + ws[p][2][1] + ws[p][3][1]
                   + ws[p][4][1] + ws[p][5][1] + ws[p][6][1] + ws[p][7][1];
        float seg4 = ws[p][0][2] + ws[p][1][2] + ws[p][2][2] + ws[p][3][2]
                   + ws[p][4][2] + ws[p][5][2] + ws[p][6][2] + ws[p][7][2];

        float c0 = seg0;
        float c1 = c0 + seg1;
        float c2 = c1 + seg2;
        float c3 = c2 + seg3;
        float c4 = c3 + seg4;

        float r0 = rsqrtf(c0 * (1.0f / 256.0f)  + EPS);
        float r1 = rsqrtf(c1 * (1.0f / 512.0f)  + EPS);
        float r2 = rsqrtf(c2 * (1.0f / 1024.0f) + EPS);
        float r3 = rsqrtf(c3 * (1.0f / 2048.0f) + EPS);
        float r4 = rsqrtf(c4 * (1.0f / 4096.0f) + EPS);

        float ra = (t < 64) ? r0 : (t < 128) ? r1 : r2;  // warp-uniform
        float rb = r3;
        float rc = r4;

        float4 o0, o1, o2, o3;
        o0.x = a.x * ra * s0.x;  o0.y = a.y * ra * s0.y;
        o0.z = a.z * ra * s0.z;  o0.w = a.w * ra * s0.w;
        o1.x = b.x * rb * s1.x;  o1.y = b.y * rb * s1.y;
        o1.z = b.z * rb * s1.z;  o1.w = b.w * rb * s1.w;
        o2.x = c.x * rc * s2.x;  o2.y = c.y * rc * s2.y;
        o2.z = c.z * rc * s2.z;  o2.w = c.w * rc * s2.w;
        o3.x = d.x * rc * s3.x;  o3.y = d.y * rc * s3.y;
        o3.z = d.z * rc * s3.z;  o3.w = d.w * rc * s3.w;

        __stcs(&orow[t],               o0);
        __stcs(&orow[t + THREADS],     o1);
        __stcs(&orow[t + 2 * THREADS], o2);
        __stcs(&orow[t + 3 * THREADS], o3);
        // No trailing barrier: next iteration writes ws[p^1], and the parity
        // buffer isn't rewritten until after another barrier has passed.
    }
}

extern "C" void kernel_launch(void* const* d_in, const int* in_sizes, int n_in,
                              void* d_out, int out_size)
{
    const float4* x = (const float4*)d_in[0];
    const float4* scale = (const float4*)d_in[1];
    float4* out = (float4*)d_out;

    const int rows = out_size / D;   // 16384
    mrmsnorm_kernel<<<GRID, THREADS>>>(x, scale, out, rows);
}

// round 6
// speedup vs baseline: 1.1448x; 1.1448x over previous
#include <cuda_runtime.h>

#define D 4096
#define NV4 (D / 4)        // 1024 float4 per row
#define THREADS 256
#define EPS 1e-6f

__global__ __launch_bounds__(THREADS) void mrmsnorm_kernel(
    const float4* __restrict__ x,
    const float4* __restrict__ scale,
    float4* __restrict__ out)
{
    __shared__ float ws[2][8][3];    // [row in pair][warp][slice]

    const int t = threadIdx.x;
    const int warp = t >> 5;
    const int lane = t & 31;

    const size_t row0 = (size_t)blockIdx.x * 2;
    const float4* __restrict__ xr0 = x + row0 * NV4;
    const float4* __restrict__ xr1 = xr0 + NV4;

    // Front-issue ALL 8 streaming loads (two full rows) before any compute:
    // 8 independent LDG.128 in flight per thread.
    float4 a0 = __ldcs(&xr0[t]);
    float4 a1 = __ldcs(&xr0[t + THREADS]);
    float4 a2 = __ldcs(&xr0[t + 2 * THREADS]);
    float4 a3 = __ldcs(&xr0[t + 3 * THREADS]);
    float4 b0 = __ldcs(&xr1[t]);
    float4 b1 = __ldcs(&xr1[t + THREADS]);
    float4 b2 = __ldcs(&xr1[t + 2 * THREADS]);
    float4 b3 = __ldcs(&xr1[t + 3 * THREADS]);

    // Per-slice sum-of-squares, both rows.
    float pa0 = a0.x * a0.x + a0.y * a0.y + a0.z * a0.z + a0.w * a0.w;
    float pa1 = a1.x * a1.x + a1.y * a1.y + a1.z * a1.z + a1.w * a1.w;
    float pa2 = a2.x * a2.x + a2.y * a2.y + a2.z * a2.z + a2.w * a2.w
              + a3.x * a3.x + a3.y * a3.y + a3.z * a3.z + a3.w * a3.w;
    float pb0 = b0.x * b0.x + b0.y * b0.y + b0.z * b0.z + b0.w * b0.w;
    float pb1 = b1.x * b1.x + b1.y * b1.y + b1.z * b1.z + b1.w * b1.w;
    float pb2 = b2.x * b2.x + b2.y * b2.y + b2.z * b2.z + b2.w * b2.w
              + b3.x * b3.x + b3.y * b3.y + b3.z * b3.z + b3.w * b3.w;

    #pragma unroll
    for (int o = 16; o > 0; o >>= 1) {
        pa0 += __shfl_down_sync(0xffffffffu, pa0, o);
        pa1 += __shfl_down_sync(0xffffffffu, pa1, o);
        pa2 += __shfl_down_sync(0xffffffffu, pa2, o);
        pb0 += __shfl_down_sync(0xffffffffu, pb0, o);
        pb1 += __shfl_down_sync(0xffffffffu, pb1, o);
        pb2 += __shfl_down_sync(0xffffffffu, pb2, o);
    }

    if (lane == 0) {
        ws[0][warp][0] = pa0;
        ws[0][warp][1] = pa1;
        ws[0][warp][2] = pa2;
        ws[1][warp][0] = pb0;
        ws[1][warp][1] = pb1;
        ws[1][warp][2] = pb2;
    }
    __syncthreads();   // single barrier for BOTH rows

    // Segment sums per row; float4-index ranges: seg0 [0,64) (warps 0-1),
    // seg1 [64,128) (warps 2-3), seg2 [128,256) (warps 4-7),
    // seg3 [256,512) (slice 1), seg4 [512,1024) (slices 2,3).
    float ra_, rb_, rc_, qa_, qb_, qc_;
    {
        float seg0 = ws[0][0][0] + ws[0][1][0];
        float seg1 = ws[0][2][0] + ws[0][3][0];
        float seg2 = ws[0][4][0] + ws[0][5][0] + ws[0][6][0] + ws[0][7][0];
        float seg3 = ws[0][0][1] + ws[0][1][1] + ws[0][2][1] + ws[0][3][1]
                   + ws[0][4][1] + ws[0][5][1] + ws[0][6][1] + ws[0][7][1];
        float seg4 = ws[0][0][2] + ws[0][1][2] + ws[0][2][2] + ws[0][3][2]
                   + ws[0][4][2] + ws[0][5][2] + ws[0][6][2] + ws[0][7][2];
        float c0 = seg0, c1 = c0 + seg1, c2 = c1 + seg2, c3 = c2 + seg3, c4 = c3 + seg4;
        float r0 = rsqrtf(c0 * (1.0f / 256.0f)  + EPS);
        float r1 = rsqrtf(c1 * (1.0f / 512.0f)  + EPS);
        float r2 = rsqrtf(c2 * (1.0f / 1024.0f) + EPS);
        ra_ = (t < 64) ? r0 : (t < 128) ? r1 : r2;   // warp-uniform
        rb_ = rsqrtf(c3 * (1.0f / 2048.0f) + EPS);
        rc_ = rsqrtf(c4 * (1.0f / 4096.0f) + EPS);
    }
    {
        float seg0 = ws[1][0][0] + ws[1][1][0];
        float seg1 = ws[1][2][0] + ws[1][3][0];
        float seg2 = ws[1][4][0] + ws[1][5][0] + ws[1][6][0] + ws[1][7][0];
        float seg3 = ws[1][0][1] + ws[1][1][1] + ws[1][2][1] + ws[1][3][1]
                   + ws[1][4][1] + ws[1][5][1] + ws[1][6][1] + ws[1][7][1];
        float seg4 = ws[1][0][2] + ws[1][1][2] + ws[1][2][2] + ws[1][3][2]
                   + ws[1][4][2] + ws[1][5][2] + ws[1][6][2] + ws[1][7][2];
        float c0 = seg0, c1 = c0 + seg1, c2 = c1 + seg2, c3 = c2 + seg3, c4 = c3 + seg4;
        float r0 = rsqrtf(c0 * (1.0f / 256.0f)  + EPS);
        float r1 = rsqrtf(c1 * (1.0f / 512.0f)  + EPS);
        float r2 = rsqrtf(c2 * (1.0f / 1024.0f) + EPS);
        qa_ = (t < 64) ? r0 : (t < 128) ? r1 : r2;
        qb_ = rsqrtf(c3 * (1.0f / 2048.0f) + EPS);
        qc_ = rsqrtf(c4 * (1.0f / 4096.0f) + EPS);
    }

    float4* __restrict__ or0 = out + row0 * NV4;
    float4* __restrict__ or1 = or0 + NV4;

    // Row 0 stores (scale re-read via __ldg: L1-resident, saves registers).
    {
        float4 s = __ldg(&scale[t]);
        float4 o;
        o.x = a0.x * ra_ * s.x;  o.y = a0.y * ra_ * s.y;
        o.z = a0.z * ra_ * s.z;  o.w = a0.w * ra_ * s.w;
        __stcs(&or0[t], o);
        float4 p;
        p.x = b0.x * qa_ * s.x;  p.y = b0.y * qa_ * s.y;
        p.z = b0.z * qa_ * s.z;  p.w = b0.w * qa_ * s.w;
        __stcs(&or1[t], p);
    }
    {
        float4 s = __ldg(&scale[t + THREADS]);
        float4 o;
        o.x = a1.x * rb_ * s.x;  o.y = a1.y * rb_ * s.y;
        o.z = a1.z * rb_ * s.z;  o.w = a1.w * rb_ * s.w;
        __stcs(&or0[t + THREADS], o);
        float4 p;
        p.x = b1.x * qb_ * s.x;  p.y = b1.y * qb_ * s.y;
        p.z = b1.z * qb_ * s.z;  p.w = b1.w * qb_ * s.w;
        __stcs(&or1[t + THREADS], p);
    }
    {
        float4 s = __ldg(&scale[t + 2 * THREADS]);
        float4 o;
        o.x = a2.x * rc_ * s.x;  o.y = a2.y * rc_ * s.y;
        o.z = a2.z * rc_ * s.z;  o.w = a2.w * rc_ * s.w;
        __stcs(&or0[t + 2 * THREADS], o);
        float4 p;
        p.x = b2.x * qc_ * s.x;  p.y = b2.y * qc_ * s.y;
        p.z = b2.z * qc_ * s.z;  p.w = b2.w * qc_ * s.w;
        __stcs(&or1[t + 2 * THREADS], p);
    }
    {
        float4 s = __ldg(&scale[t + 3 * THREADS]);
        float4 o;
        o.x = a3.x * rc_ * s.x;  o.y = a3.y * rc_ * s.y;
        o.z = a3.z * rc_ * s.z;  o.w = a3.w * rc_ * s.w;
        __stcs(&or0[t + 3 * THREADS], o);
        float4 p;
        p.x = b3.x * qc_ * s.x;  p.y = b3.y * qc_ * s.y;
        p.z = b3.z * qc_ * s.z;  p.w = b3.w * qc_ * s.w;
        __stcs(&or1[t + 3 * THREADS], p);
    }
}

extern "C" void kernel_launch(void* const* d_in, const int* in_sizes, int n_in,
                              void* d_out, int out_size)
{
    const float4* x = (const float4*)d_in[0];
    const float4* scale = (const float4*)d_in[1];
    float4* out = (float4*)d_out;

    const int rows = out_size / D;   // 16384
    mrmsnorm_kernel<<<rows / 2, THREADS>>>(x, scale, out);
}